// round 15
// baseline (speedup 1.0000x reference)
#include <cuda_runtime.h>
#include <stdint.h>

// keep[b][n] = 1 if node n is in the top-k of batch b. B=16, N=2048.
__device__ unsigned char g_keep[16 * 2048];

// ---------------------------------------------------------------------------
// FINAL KERNEL (converged; best measured 86.0us, reproduced 86.0-86.8us).
// Design record:
//  - out = adj * (keep_row OR keep_col): 537MB stream -> bandwidth-bound.
//  - apply_mask runs at 6.3TB/s (~80% HBM spec), the measured sm_103a
//    LTS practical ceiling; all shape/hint variants land 75.3-76.3us.
//  - top-k: 8-bit radix select, warp-shfl bin scan, ~3us; bit-exact
//    jax.lax.top_k semantics (value desc, ties -> lower index).
//  - PDL overlaps topk with apply_mask launch + wave-1 prefetch (-18us).
//  - Fusion rejected on 4-point evidence matrix: consumer threadfence
//    flushes L1 (CCTL.IVALL), reg caps spill, honest regs kill occupancy.
// ---------------------------------------------------------------------------
__global__ void __launch_bounds__(256)
topk_radix_kernel(const float* __restrict__ score, int N, int k) {
    __shared__ unsigned u[2048];
    __shared__ unsigned hist[256];
    __shared__ unsigned s_prefix, s_kk;

    const int b   = blockIdx.x;
    const int tid = threadIdx.x;
    const float* sc = score + (size_t)b * N;

    for (int t = tid; t < N; t += 256) {
        unsigned x = __float_as_uint(sc[t]);
        x ^= (x & 0x80000000u) ? 0xFFFFFFFFu : 0x80000000u;  // order-preserving
        u[t] = x;
    }
    if (tid == 0) { s_prefix = 0u; s_kk = (unsigned)k; }
    __syncthreads();

    for (int shift = 24; shift >= 0; shift -= 8) {
        const unsigned prefix = s_prefix;
        const unsigned kk     = s_kk;
        const unsigned pmask  = (shift == 24) ? 0u : (0xFFFFFFFFu << (shift + 8));

        hist[tid] = 0u;
        __syncthreads();

        for (int t = tid; t < N; t += 256) {
            unsigned x = u[t];
            if ((x & pmask) == prefix)
                atomicAdd(&hist[(x >> shift) & 0xFFu], 1u);
        }
        __syncthreads();

        // single-warp suffix scan over 256 bins: r = 255 - bin
        if (tid < 32) {
            unsigned v[8], p[8];
            unsigned acc = 0u;
#pragma unroll
            for (int i = 0; i < 8; i++) {
                v[i] = hist[255 - (tid * 8 + i)];
                acc += v[i];
                p[i] = acc;                       // lane-local inclusive prefix
            }
            unsigned lane_excl = 0u, run = acc;
#pragma unroll
            for (int off = 1; off < 32; off <<= 1) {
                unsigned n0 = __shfl_up_sync(0xFFFFFFFFu, run, off);
                if ((int)(tid) >= off) { lane_excl += n0; run += n0; }
            }
#pragma unroll
            for (int i = 0; i < 8; i++) {
                unsigned incl = lane_excl + p[i];
                unsigned excl = incl - v[i];
                if (excl < kk && incl >= kk) {    // unique r
                    int bin = 255 - (tid * 8 + i);
                    s_prefix = prefix | ((unsigned)bin << shift);
                    s_kk     = kk - excl;
                }
            }
        }
        __syncthreads();
    }

    const unsigned T        = s_prefix;          // exact k-th largest pattern
    const unsigned need_eq  = s_kk;              // equals to keep (>=1)
    const unsigned total_eq = hist[T & 0xFFu];   // exact equal count (last level)

    for (int t = tid; t < N; t += 256) {
        unsigned x = u[t];
        unsigned char kp = 0u;
        if (x > T) {
            kp = 1u;
        } else if (x == T) {
            if (total_eq == need_eq) {
                kp = 1u;                         // common path: keep all equals
            } else {
                unsigned c = 0u;                 // rare: rank among equals by index
                for (int j = 0; j < t; j++) c += (u[j] == T);
                kp = (c < need_eq) ? 1u : 0u;
            }
        }
        g_keep[b * N + t] = kp;
    }

    __threadfence();
    __syncthreads();
    if (tid == 0) cudaTriggerProgrammaticLaunchCompletion();
}

// ---------------------------------------------------------------------------
// Kernel 2: out[b,i,j] = adj[b,i,j] * (keep[b,i] || keep[b,j])
// PDL secondary: prefetch adj BEFORE cudaGridDependencySynchronize() so
// launch latency + wave-1 global loads overlap the topk kernel.
// 1 row per block, 256 threads, 2 float4 per thread, 32 regs.
// ---------------------------------------------------------------------------
__global__ void apply_mask_kernel(const float4* __restrict__ adj,
                                  float4* __restrict__ out, int N) {
    int row = blockIdx.x;              // 0 .. B*N-1
    int b   = row / N;
    int i   = row - b * N;

    int    nvec = N >> 2;
    size_t base = (size_t)row * nvec;

    int  j0 = threadIdx.x;
    int  j1 = threadIdx.x + blockDim.x;
    bool h0 = j0 < nvec;
    bool h1 = j1 < nvec;

    float4 v0 = {0,0,0,0}, v1 = {0,0,0,0};
    if (h0) v0 = adj[base + j0];
    if (h1) v1 = adj[base + j1];

    cudaGridDependencySynchronize();   // wait for g_keep (overlapped w/ loads)

    const unsigned char* kb = g_keep + b * N;
    const uchar4*        km = (const uchar4*)kb;  // 2KB, L1-resident
    bool row_kept = (kb[i] != 0);

    if (!row_kept) {
        if (h0) {
            uchar4 m = km[j0];
            v0.x = m.x ? v0.x : 0.0f;  v0.y = m.y ? v0.y : 0.0f;
            v0.z = m.z ? v0.z : 0.0f;  v0.w = m.w ? v0.w : 0.0f;
        }
        if (h1) {
            uchar4 m = km[j1];
            v1.x = m.x ? v1.x : 0.0f;  v1.y = m.y ? v1.y : 0.0f;
            v1.z = m.z ? v1.z : 0.0f;  v1.w = m.w ? v1.w : 0.0f;
        }
    }
    if (h0) out[base + j0] = v0;
    if (h1) out[base + j1] = v1;

    // generic tail (unused for N=2048 with 256 threads)
    for (int j = threadIdx.x + 2 * blockDim.x; j < nvec; j += blockDim.x) {
        float4 v = adj[base + j];
        if (!row_kept) {
            uchar4 m = km[j];
            v.x = m.x ? v.x : 0.0f;  v.y = m.y ? v.y : 0.0f;
            v.z = m.z ? v.z : 0.0f;  v.w = m.w ? v.w : 0.0f;
        }
        out[base + j] = v;
    }
}

extern "C" void kernel_launch(void* const* d_in, const int* in_sizes, int n_in,
                              void* d_out, int out_size) {
    const float* adj   = (const float*)d_in[0];   // [B, N, N] fp32
    const float* score = (const float*)d_in[1];   // [B, N, 1] fp32

    long long n_adj   = in_sizes[0];
    long long n_score = in_sizes[1];
    int N = (int)(n_adj / n_score);               // 2048
    int B = (int)(n_score / N);                   // 16
    int k = N / 2;                                // RATE = 0.5

    topk_radix_kernel<<<B, 256>>>(score, N, k);

    // Secondary with Programmatic Stream Serialization (PDL).
    cudaLaunchConfig_t cfg = {};
    cfg.gridDim  = dim3((unsigned)(B * N));
    cfg.blockDim = dim3(256);
    cfg.stream   = 0;
    cudaLaunchAttribute attr[1];
    attr[0].id = cudaLaunchAttributeProgrammaticStreamSerialization;
    attr[0].val.programmaticStreamSerializationAllowed = 1;
    cfg.attrs    = attr;
    cfg.numAttrs = 1;
    cudaLaunchKernelEx(&cfg, apply_mask_kernel,
                       (const float4*)adj, (float4*)d_out, N);
}

// round 16
// speedup vs baseline: 1.0063x; 1.0063x over previous
#include <cuda_runtime.h>
#include <stdint.h>

// keep[b][n] = 1 if node n is in the top-k of batch b. B=16, N=2048.
__device__ unsigned char g_keep[16 * 2048];

// ---------------------------------------------------------------------------
// FINAL KERNEL (converged; 86.0us best, 86.0-86.8us over 4 reproductions).
// Design record:
//  - out = adj * (keep_row OR keep_col): 537MB irreducible stream.
//  - apply_mask: 6.3-6.5TB/s (80-82% HBM spec) = measured sm_103a LTS
//    practical ceiling; all shape/hint variants land 73.9-76.3us (noise).
//  - top-k: 8-bit radix select, warp-shfl bin suffix-scan, ~3us; bit-exact
//    jax.lax.top_k semantics (value desc, ties -> lower index).
//  - PDL overlaps topk with apply_mask launch + wave-1 prefetch (-18us).
//  - Fusion rejected on 4-variant evidence matrix (fence L1-flush, spills,
//    reg-pressure occupancy loss); concurrent-stream spin rejected
//    (producer-starvation deadlock risk under a 32768-block grid).
// ---------------------------------------------------------------------------
__global__ void __launch_bounds__(256)
topk_radix_kernel(const float* __restrict__ score, int N, int k) {
    __shared__ unsigned u[2048];
    __shared__ unsigned hist[256];
    __shared__ unsigned s_prefix, s_kk;

    const int b   = blockIdx.x;
    const int tid = threadIdx.x;
    const float* sc = score + (size_t)b * N;

    for (int t = tid; t < N; t += 256) {
        unsigned x = __float_as_uint(sc[t]);
        x ^= (x & 0x80000000u) ? 0xFFFFFFFFu : 0x80000000u;  // order-preserving
        u[t] = x;
    }
    if (tid == 0) { s_prefix = 0u; s_kk = (unsigned)k; }
    __syncthreads();

    for (int shift = 24; shift >= 0; shift -= 8) {
        const unsigned prefix = s_prefix;
        const unsigned kk     = s_kk;
        const unsigned pmask  = (shift == 24) ? 0u : (0xFFFFFFFFu << (shift + 8));

        hist[tid] = 0u;
        __syncthreads();

        for (int t = tid; t < N; t += 256) {
            unsigned x = u[t];
            if ((x & pmask) == prefix)
                atomicAdd(&hist[(x >> shift) & 0xFFu], 1u);
        }
        __syncthreads();

        // single-warp suffix scan over 256 bins: r = 255 - bin
        if (tid < 32) {
            unsigned v[8], p[8];
            unsigned acc = 0u;
#pragma unroll
            for (int i = 0; i < 8; i++) {
                v[i] = hist[255 - (tid * 8 + i)];
                acc += v[i];
                p[i] = acc;                       // lane-local inclusive prefix
            }
            unsigned lane_excl = 0u, run = acc;
#pragma unroll
            for (int off = 1; off < 32; off <<= 1) {
                unsigned n0 = __shfl_up_sync(0xFFFFFFFFu, run, off);
                if ((int)(tid) >= off) { lane_excl += n0; run += n0; }
            }
#pragma unroll
            for (int i = 0; i < 8; i++) {
                unsigned incl = lane_excl + p[i];
                unsigned excl = incl - v[i];
                if (excl < kk && incl >= kk) {    // unique r
                    int bin = 255 - (tid * 8 + i);
                    s_prefix = prefix | ((unsigned)bin << shift);
                    s_kk     = kk - excl;
                }
            }
        }
        __syncthreads();
    }

    const unsigned T        = s_prefix;          // exact k-th largest pattern
    const unsigned need_eq  = s_kk;              // equals to keep (>=1)
    const unsigned total_eq = hist[T & 0xFFu];   // exact equal count (last level)

    for (int t = tid; t < N; t += 256) {
        unsigned x = u[t];
        unsigned char kp = 0u;
        if (x > T) {
            kp = 1u;
        } else if (x == T) {
            if (total_eq == need_eq) {
                kp = 1u;                         // common path: keep all equals
            } else {
                unsigned c = 0u;                 // rare: rank among equals by index
                for (int j = 0; j < t; j++) c += (u[j] == T);
                kp = (c < need_eq) ? 1u : 0u;
            }
        }
        g_keep[b * N + t] = kp;
    }

    __threadfence();
    __syncthreads();
    if (tid == 0) cudaTriggerProgrammaticLaunchCompletion();
}

// ---------------------------------------------------------------------------
// Kernel 2: out[b,i,j] = adj[b,i,j] * (keep[b,i] || keep[b,j])
// PDL secondary: prefetch adj BEFORE cudaGridDependencySynchronize() so
// launch latency + wave-1 global loads overlap the topk kernel.
// 1 row per block, 256 threads, 2 float4 per thread, 32 regs.
// ---------------------------------------------------------------------------
__global__ void apply_mask_kernel(const float4* __restrict__ adj,
                                  float4* __restrict__ out, int N) {
    int row = blockIdx.x;              // 0 .. B*N-1
    int b   = row / N;
    int i   = row - b * N;

    int    nvec = N >> 2;
    size_t base = (size_t)row * nvec;

    int  j0 = threadIdx.x;
    int  j1 = threadIdx.x + blockDim.x;
    bool h0 = j0 < nvec;
    bool h1 = j1 < nvec;

    float4 v0 = {0,0,0,0}, v1 = {0,0,0,0};
    if (h0) v0 = adj[base + j0];
    if (h1) v1 = adj[base + j1];

    cudaGridDependencySynchronize();   // wait for g_keep (overlapped w/ loads)

    const unsigned char* kb = g_keep + b * N;
    const uchar4*        km = (const uchar4*)kb;  // 2KB, L1-resident
    bool row_kept = (kb[i] != 0);

    if (!row_kept) {
        if (h0) {
            uchar4 m = km[j0];
            v0.x = m.x ? v0.x : 0.0f;  v0.y = m.y ? v0.y : 0.0f;
            v0.z = m.z ? v0.z : 0.0f;  v0.w = m.w ? v0.w : 0.0f;
        }
        if (h1) {
            uchar4 m = km[j1];
            v1.x = m.x ? v1.x : 0.0f;  v1.y = m.y ? v1.y : 0.0f;
            v1.z = m.z ? v1.z : 0.0f;  v1.w = m.w ? v1.w : 0.0f;
        }
    }
    if (h0) out[base + j0] = v0;
    if (h1) out[base + j1] = v1;

    // generic tail (unused for N=2048 with 256 threads)
    for (int j = threadIdx.x + 2 * blockDim.x; j < nvec; j += blockDim.x) {
        float4 v = adj[base + j];
        if (!row_kept) {
            uchar4 m = km[j];
            v.x = m.x ? v.x : 0.0f;  v.y = m.y ? v.y : 0.0f;
            v.z = m.z ? v.z : 0.0f;  v.w = m.w ? v.w : 0.0f;
        }
        out[base + j] = v;
    }
}

extern "C" void kernel_launch(void* const* d_in, const int* in_sizes, int n_in,
                              void* d_out, int out_size) {
    const float* adj   = (const float*)d_in[0];   // [B, N, N] fp32
    const float* score = (const float*)d_in[1];   // [B, N, 1] fp32

    long long n_adj   = in_sizes[0];
    long long n_score = in_sizes[1];
    int N = (int)(n_adj / n_score);               // 2048
    int B = (int)(n_score / N);                   // 16
    int k = N / 2;                                // RATE = 0.5

    topk_radix_kernel<<<B, 256>>>(score, N, k);

    // Secondary with Programmatic Stream Serialization (PDL).
    cudaLaunchConfig_t cfg = {};
    cfg.gridDim  = dim3((unsigned)(B * N));
    cfg.blockDim = dim3(256);
    cfg.stream   = 0;
    cudaLaunchAttribute attr[1];
    attr[0].id = cudaLaunchAttributeProgrammaticStreamSerialization;
    attr[0].val.programmaticStreamSerializationAllowed = 1;
    cfg.attrs    = attr;
    cfg.numAttrs = 1;
    cudaLaunchKernelEx(&cfg, apply_mask_kernel,
                       (const float4*)adj, (float4*)d_out, N);
}